// round 11
// baseline (speedup 1.0000x reference)
#include <cuda_runtime.h>
#include <cuda_fp16.h>

#define NG   64
#define MAXN 100000
#define MAXE 3200000
#define MAX_SCAN_BLOCKS 128

// ---------------- scratch (device globals; no allocation allowed) ----------------
__device__ __align__(16) __half2 g_h1h[MAXN * 8];   // h1 as half2 (16 ch)
__device__ __align__(16) float g_as1 [MAXN * 4];
__device__ __align__(16) float g_ad1 [MAXN * 4];
__device__ __align__(16) __half2 g_v2h[MAXN * 16];  // v2 as half2 (32 ch)
__device__ __align__(16) __half2 g_out2h[MAXN * 16];// out2 (post-mish) as half2
__device__ float g_as2[MAXN];
__device__ float g_ad2[MAXN];
__device__ int   g_deg[MAXN];
__device__ int   g_rowstart[MAXN];
__device__ int   g_cursor[MAXN];
__device__ int   g_srcs[MAXE];
__device__ int   g_bsums[MAX_SCAN_BLOCKS];
__device__ __align__(16) float g_sums[NG * 32];
__device__ int   g_cnt[NG];

// ---------------- helpers ----------------
__device__ __forceinline__ float leakyf(float x) { return x > 0.f ? x : 0.2f * x; }

__device__ __forceinline__ float mishf(float x) {
    float sp = fmaxf(x, 0.f) + log1pf(expf(-fabsf(x)));
    return x * tanhf(sp);
}

__device__ __forceinline__ void fma4(float4& a, float s, float4 b) {
    a.x += s * b.x; a.y += s * b.y; a.z += s * b.z; a.w += s * b.w;
}
__device__ __forceinline__ float dot4(float4 a, float4 b) {
    return a.x * b.x + a.y * b.y + a.z * b.z + a.w * b.w;
}
__device__ __forceinline__ float4 ldg4(const float* p) {
    return __ldg((const float4*)p);
}

// ---------------- CSR build ----------------
__global__ void k_zero(int N) {
    int t = blockIdx.x * blockDim.x + threadIdx.x;
    if (t < N)       g_deg[t]  = 0;
    if (t < NG * 32) g_sums[t] = 0.f;
    if (t < NG)      g_cnt[t]  = 0;
}

__global__ __launch_bounds__(256) void k_hist(const int* __restrict__ ei, int E) {
    int base = (blockIdx.x * 256 + threadIdx.x) * 4;
#pragma unroll
    for (int k = 0; k < 4; k++) {
        int t = base + k;
        if (t < E) atomicAdd(&g_deg[__ldg(&ei[E + t])], 1);
    }
}

__global__ __launch_bounds__(1024) void k_scan1(int N) {
    __shared__ int ws[32];
    int t = threadIdx.x, lane = t & 31, wid = t >> 5;
    int i = blockIdx.x * 1024 + t;
    int v = (i < N) ? g_deg[i] : 0;
#pragma unroll
    for (int o = 16; o > 0; o >>= 1) v += __shfl_down_sync(0xffffffffu, v, o);
    if (lane == 0) ws[wid] = v;
    __syncthreads();
    if (wid == 0) {
        int u = ws[lane];
#pragma unroll
        for (int o = 16; o > 0; o >>= 1) u += __shfl_down_sync(0xffffffffu, u, o);
        if (lane == 0) g_bsums[blockIdx.x] = u;
    }
}

__global__ __launch_bounds__(1024) void k_scan3(int N, int nb) {
    __shared__ int sbs[MAX_SCAN_BLOCKS];
    __shared__ int ws[32];
    int t = threadIdx.x, lane = t & 31, wid = t >> 5;

    if (wid == 0) {
        int acc = 0;
#pragma unroll
        for (int c = 0; c < 4; c++) {
            int idx = c * 32 + lane;
            int v = (idx < nb) ? g_bsums[idx] : 0;
#pragma unroll
            for (int o = 1; o < 32; o <<= 1) {
                int u = __shfl_up_sync(0xffffffffu, v, o);
                if (lane >= o) v += u;
            }
            v += acc;
            sbs[idx] = v;
            acc = __shfl_sync(0xffffffffu, v, 31);
        }
    }

    int i = blockIdx.x * 1024 + t;
    int orig = (i < N) ? g_deg[i] : 0;
    int v = orig;
#pragma unroll
    for (int o = 1; o < 32; o <<= 1) {
        int u = __shfl_up_sync(0xffffffffu, v, o);
        if (lane >= o) v += u;
    }
    if (lane == 31) ws[wid] = v;
    __syncthreads();
    if (wid == 0) {
        int u = ws[lane];
#pragma unroll
        for (int o = 1; o < 32; o <<= 1) {
            int w2 = __shfl_up_sync(0xffffffffu, u, o);
            if (lane >= o) u += w2;
        }
        ws[lane] = u;
    }
    __syncthreads();
    int woff = (wid == 0) ? 0 : ws[wid - 1];
    int boff = (blockIdx.x == 0) ? 0 : sbs[blockIdx.x - 1];
    if (i < N) {
        int excl = boff + woff + v - orig;
        g_rowstart[i] = excl;
        g_cursor[i]   = excl;
    }
}

__global__ __launch_bounds__(256) void k_scatter(const int* __restrict__ ei, int E) {
    int base = (blockIdx.x * 256 + threadIdx.x) * 4;
#pragma unroll
    for (int k = 0; k < 4; k++) {
        int t = base + k;
        if (t < E) {
            int s = __ldg(&ei[t]);
            int d = __ldg(&ei[E + t]);
            int pos = atomicAdd(&g_cursor[d], 1);
            g_srcs[pos] = s;
        }
    }
}

// ---------------- Layer 1: cooperative GEMM, 4 threads/node ----------------
// Coalesced x loads (warp touches 8 lines/LDG, not 32); W1 transposed into
// padded smem rows (132 floats) so the 4 sub-lanes hit disjoint bank groups.
__global__ __launch_bounds__(256) void k_gemm1(
    const float* __restrict__ x, const float* __restrict__ W1,
    const float* __restrict__ asw, const float* __restrict__ adw, int N)
{
    __shared__ float W1t[16 * 132];   // W1t[j*132 + k], padded pitch
    __shared__ float As[16], Ad[16];
    int tid = threadIdx.x;
    for (int i = tid; i < 2048; i += 256) {
        int k = i >> 4, j = i & 15;
        W1t[j * 132 + k] = W1[i];
    }
    if (tid < 16) { As[tid] = asw[tid]; Ad[tid] = adw[tid]; }
    __syncthreads();

    int node = (blockIdx.x * 256 + tid) >> 2;
    int q = tid & 3;                  // sub-lane; also the head this lane keeps
    if (node >= N) return;

    const float4* xr = (const float4*)(x + (size_t)node * 128);
    float acc[16];
#pragma unroll
    for (int j = 0; j < 16; j++) acc[j] = 0.f;

#pragma unroll
    for (int i = 0; i < 8; i++) {
        int k4 = q + 4 * i;           // float4 index within the row
        float4 xv = __ldg(xr + k4);
#pragma unroll
        for (int j = 0; j < 16; j++) {
            float4 wv = *(const float4*)&W1t[j * 132 + k4 * 4];
            acc[j] += xv.x * wv.x + xv.y * wv.y + xv.z * wv.z + xv.w * wv.w;
        }
    }

    // reduce partials across the 4 sub-lanes (lane groups are 4-aligned)
#pragma unroll
    for (int j = 0; j < 16; j++) {
        acc[j] += __shfl_xor_sync(0xffffffffu, acc[j], 1);
        acc[j] += __shfl_xor_sync(0xffffffffu, acc[j], 2);
    }

    // lane q keeps head q (channels 4q..4q+3); logits computed locally
    float4 hh = make_float4(acc[q*4+0], acc[q*4+1], acc[q*4+2], acc[q*4+3]);
    float4 av = *(const float4*)&As[q * 4];
    float4 bv = *(const float4*)&Ad[q * 4];
    float asv = dot4(hh, av);
    float adv = dot4(hh, bv);

    __half2* h1p = g_h1h + (size_t)node * 8 + q * 2;
    h1p[0] = __floats2half2_rn(hh.x, hh.y);
    h1p[1] = __floats2half2_rn(hh.z, hh.w);
    g_as1[node * 4 + q] = asv;
    g_ad1[node * 4 + q] = adv;
}

// ---------------- Layer 1 aggregation + FUSED layer-2 node stage (R8/R10 form) ----------------
__global__ __launch_bounds__(256) void k_agg1(
    const float* __restrict__ W2, const float* __restrict__ b1,
    const float* __restrict__ a2s, const float* __restrict__ a2d, int N)
{
    __shared__ float W2s[16 * 32];
    __shared__ float A2[32], B2[32], b1s[16];
    int tid = threadIdx.x;
    for (int i = tid; i < 512; i += 256) W2s[i] = W2[i];
    if (tid < 32) { A2[tid] = a2s[tid]; B2[tid] = a2d[tid]; }
    if (tid < 16) b1s[tid] = b1[tid];
    __syncthreads();

    int gid = blockIdx.x * 256 + tid;
    int d = gid >> 3;
    if (d >= N) return;
    int l = tid & 7;    // channel pair 0..7 (channels 2l, 2l+1)
    int h = l >> 1;     // head 0..3
    unsigned gmask = 0xffu << (tid & 24);

    float adh = g_ad1[d * 4 + h];
    float ash = g_as1[d * 4 + h];
    float2 hv0 = __half22float2(g_h1h[d * 8 + l]);
    float ee0 = expf(leakyf(ash + adh));   // self-loop
    float accx = ee0 * hv0.x, accy = ee0 * hv0.y;
    float den = ee0;

    int start = g_rowstart[d];
    int deg   = g_deg[d];
    int j = 0;
    for (; j + 4 <= deg; j += 4) {
        int s0 = __ldg(&g_srcs[start + j + 0]);
        int s1 = __ldg(&g_srcs[start + j + 1]);
        int s2 = __ldg(&g_srcs[start + j + 2]);
        int s3 = __ldg(&g_srcs[start + j + 3]);
        float a0 = __ldg(&g_as1[s0 * 4 + h]);
        float a1 = __ldg(&g_as1[s1 * 4 + h]);
        float a2 = __ldg(&g_as1[s2 * 4 + h]);
        float a3 = __ldg(&g_as1[s3 * 4 + h]);
        __half2 f0 = __ldg(&g_h1h[s0 * 8 + l]);
        __half2 f1 = __ldg(&g_h1h[s1 * 8 + l]);
        __half2 f2 = __ldg(&g_h1h[s2 * 8 + l]);
        __half2 f3 = __ldg(&g_h1h[s3 * 8 + l]);
        float e0 = expf(leakyf(a0 + adh));
        float e1 = expf(leakyf(a1 + adh));
        float e2 = expf(leakyf(a2 + adh));
        float e3 = expf(leakyf(a3 + adh));
        float2 g0 = __half22float2(f0), g1 = __half22float2(f1);
        float2 g2 = __half22float2(f2), g3 = __half22float2(f3);
        accx += e0 * g0.x + e1 * g1.x + e2 * g2.x + e3 * g3.x;
        accy += e0 * g0.y + e1 * g1.y + e2 * g2.y + e3 * g3.y;
        den  += (e0 + e1) + (e2 + e3);
    }
    for (; j < deg; j++) {
        int s = __ldg(&g_srcs[start + j]);
        float a = __ldg(&g_as1[s * 4 + h]);
        __half2 f = __ldg(&g_h1h[s * 8 + l]);
        float e = expf(leakyf(a + adh));
        float2 g = __half22float2(f);
        accx += e * g.x; accy += e * g.y; den += e;
    }

    // ---- fused layer-2 node stage ----
    float inv = 1.f / (den + 1e-16f);
    float h2a = mishf(accx * inv + b1s[2 * l]);
    float h2b = mishf(accy * inv + b1s[2 * l + 1]);

    float4 v = make_float4(0.f, 0.f, 0.f, 0.f);
#pragma unroll
    for (int k = 0; k < 16; k++) {
        float hk = (k & 1) ? __shfl_sync(gmask, h2b, k >> 1, 8)
                           : __shfl_sync(gmask, h2a, k >> 1, 8);
        fma4(v, hk, *(const float4*)&W2s[k * 32 + 4 * l]);
    }
    float as2 = dot4(v, *(const float4*)&A2[4 * l]);
    float ad2 = dot4(v, *(const float4*)&B2[4 * l]);
#pragma unroll
    for (int o = 4; o > 0; o >>= 1) {
        as2 += __shfl_xor_sync(gmask, as2, o, 8);
        ad2 += __shfl_xor_sync(gmask, ad2, o, 8);
    }

    __half2* vp = g_v2h + (size_t)d * 16 + 2 * l;
    vp[0] = __floats2half2_rn(v.x, v.y);
    vp[1] = __floats2half2_rn(v.z, v.w);
    if (l == 0) { g_as2[d] = as2; g_ad2[d] = ad2; }
}

// ---------------- Layer 2 aggregation, exp-deduplicated + FUSED mish epilogue ----------------
__global__ __launch_bounds__(256) void k_agg2(const float* __restrict__ b2, int N)
{
    int tid = threadIdx.x;
    int gid = blockIdx.x * 256 + tid;
    int d = gid >> 4;
    if (d >= N) return;
    int l = tid & 15;   // channel pair 0..15
    unsigned gmask = 0xffffu << (tid & 16);

    float ad  = g_ad2[d];
    float ee0 = expf(leakyf(g_as2[d] + ad));   // self-loop
    float2 vv0 = __half22float2(g_v2h[(size_t)d * 16 + l]);
    float accx = ee0 * vv0.x, accy = ee0 * vv0.y;
    float den = ee0;

    int start = g_rowstart[d];
    int deg   = g_deg[d];
    for (int j0 = 0; j0 < deg; j0 += 16) {
        int rem = deg - j0;
        int s_m = 0; float e_m = 0.f;
        if (l < rem) {
            s_m = __ldg(&g_srcs[start + j0 + l]);          // coalesced 16-wide
            e_m = expf(leakyf(__ldg(&g_as2[s_m]) + ad));   // ONE exp per edge
        }
        int kmax = min(rem, 16);
#pragma unroll 4
        for (int k = 0; k < kmax; k++) {
            int   s = __shfl_sync(gmask, s_m, k, 16);
            float e = __shfl_sync(gmask, e_m, k, 16);
            float2 g = __half22float2(__ldg(&g_v2h[(size_t)s * 16 + l]));
            accx += e * g.x; accy += e * g.y; den += e;
        }
    }

    float inv = 1.f / (den + 1e-16f);
    float oa = mishf(accx * inv + __ldg(&b2[2 * l]));
    float ob = mishf(accy * inv + __ldg(&b2[2 * l + 1]));
    g_out2h[(size_t)d * 16 + l] = __floats2half2_rn(oa, ob);
}

// ---------------- pool over half out2 ----------------
__global__ __launch_bounds__(256) void k_pool(
    const int* __restrict__ batch, int N, int chunk)
{
    __shared__ float ss[NG * 32];
    __shared__ int   sc[NG];
    int tid = threadIdx.x;
    for (int i = tid; i < NG * 32; i += 256) ss[i] = 0.f;
    if (tid < NG) sc[tid] = 0;
    __syncthreads();

    int start = blockIdx.x * chunk;
    int end   = min(N, start + chunk);
    int lane = tid & 31, w = tid >> 5;

    const __half* o2 = (const __half*)g_out2h;
    for (int node = start + w; node < end; node += 8) {
        int g = __ldg(&batch[node]);
        float val = __half2float(o2[(size_t)node * 32 + lane]);
        atomicAdd(&ss[g * 32 + lane], val);
        if (lane == 0) atomicAdd(&sc[g], 1);
    }
    __syncthreads();

    for (int i = tid; i < NG; i += 256)
        if (sc[i]) atomicAdd(&g_cnt[i], sc[i]);
    for (int i = tid; i < NG * 32; i += 256)
        if (sc[i >> 5]) atomicAdd(&g_sums[i], ss[i]);
}

__global__ void k_final(float* __restrict__ out)
{
    int t = blockIdx.x * blockDim.x + threadIdx.x;
    if (t < NG * 32)
        out[t] = g_sums[t] / fmaxf((float)g_cnt[t >> 5], 1.0f);
}

// ---------------- launch ----------------
extern "C" void kernel_launch(void* const* d_in, const int* in_sizes, int n_in,
                              void* d_out, int out_size)
{
    const float* x   = (const float*)d_in[0];
    const int*   ei  = (const int*)d_in[1];    // int32 [2,E]
    const int*   bat = (const int*)d_in[2];    // int32 [N]
    const float* W1  = (const float*)d_in[3];
    const float* b1  = (const float*)d_in[4];
    const float* a1s = (const float*)d_in[5];
    const float* a1d = (const float*)d_in[6];
    const float* W2  = (const float*)d_in[7];
    const float* b2  = (const float*)d_in[8];
    const float* a2s = (const float*)d_in[9];
    const float* a2d = (const float*)d_in[10];

    int N = in_sizes[0] / 128;
    int E = in_sizes[1] / 2;
    float* out = (float*)d_out;
    int nb = (N + 1023) / 1024;   // <=128

    // CSR build (gemm1 at profiled launch index 3)
    k_zero<<<(N + 255) / 256, 256>>>(N);
    k_hist<<<(E + 1023) / 1024, 256>>>(ei, E);
    k_scan1<<<nb, 1024>>>(N);
    k_gemm1<<<(N * 4 + 255) / 256, 256>>>(x, W1, a1s, a1d, N);
    k_scan3<<<nb, 1024>>>(N, nb);
    k_scatter<<<(E + 1023) / 1024, 256>>>(ei, E);

    // GAT layers (l2node fused into agg1; exp-dedup agg2 with fused mish)
    k_agg1<<<(N * 8 + 255) / 256, 256>>>(W2, b1, a2s, a2d, N);
    k_agg2<<<(N * 16 + 255) / 256, 256>>>(b2, N);

    int chunk = (N + 255) / 256;
    k_pool<<<256, 256>>>(bat, N, chunk);
    k_final<<<8, 256>>>(out);
}

// round 12
// speedup vs baseline: 1.0832x; 1.0832x over previous
#include <cuda_runtime.h>
#include <cuda_fp16.h>

#define NG   64
#define MAXN 100000
#define MAXE 3200000
#define MAX_SCAN_BLOCKS 128

// ---------------- scratch (device globals; no allocation allowed) ----------------
__device__ __align__(16) __half2 g_h1h[MAXN * 8];   // h1 as half2 (16 ch)
__device__ __align__(16) float g_as1 [MAXN * 4];
__device__ __align__(16) float g_ad1 [MAXN * 4];
__device__ __align__(16) __half2 g_v2h[MAXN * 16];  // v2 as half2 (32 ch)
__device__ __align__(16) __half2 g_out2h[MAXN * 16];// out2 (post-mish) as half2
__device__ float g_as2[MAXN];
__device__ float g_ad2[MAXN];
__device__ int   g_deg[MAXN];
__device__ int   g_rowstart[MAXN];
__device__ int   g_cursor[MAXN];
__device__ int   g_srcs[MAXE];
__device__ int   g_bsums[MAX_SCAN_BLOCKS];
__device__ __align__(16) float g_sums[NG * 32];
__device__ int   g_cnt[NG];

// ---------------- helpers ----------------
__device__ __forceinline__ float leakyf(float x) { return x > 0.f ? x : 0.2f * x; }

__device__ __forceinline__ float mishf(float x) {
    float sp = fmaxf(x, 0.f) + log1pf(expf(-fabsf(x)));
    return x * tanhf(sp);
}

__device__ __forceinline__ void fma4(float4& a, float s, float4 b) {
    a.x += s * b.x; a.y += s * b.y; a.z += s * b.z; a.w += s * b.w;
}
__device__ __forceinline__ float dot4(float4 a, float4 b) {
    return a.x * b.x + a.y * b.y + a.z * b.z + a.w * b.w;
}
__device__ __forceinline__ float4 ldg4(const float* p) {
    return __ldg((const float4*)p);
}

// ---------------- CSR build ----------------
__global__ void k_zero(int N) {
    int t = blockIdx.x * blockDim.x + threadIdx.x;
    if (t < N)       g_deg[t]  = 0;
    if (t < NG * 32) g_sums[t] = 0.f;
    if (t < NG)      g_cnt[t]  = 0;
}

__global__ __launch_bounds__(256) void k_hist(const int* __restrict__ ei, int E) {
    int base = (blockIdx.x * 256 + threadIdx.x) * 4;
#pragma unroll
    for (int k = 0; k < 4; k++) {
        int t = base + k;
        if (t < E) atomicAdd(&g_deg[__ldg(&ei[E + t])], 1);
    }
}

__global__ __launch_bounds__(1024) void k_scan1(int N) {
    __shared__ int ws[32];
    int t = threadIdx.x, lane = t & 31, wid = t >> 5;
    int i = blockIdx.x * 1024 + t;
    int v = (i < N) ? g_deg[i] : 0;
#pragma unroll
    for (int o = 16; o > 0; o >>= 1) v += __shfl_down_sync(0xffffffffu, v, o);
    if (lane == 0) ws[wid] = v;
    __syncthreads();
    if (wid == 0) {
        int u = ws[lane];
#pragma unroll
        for (int o = 16; o > 0; o >>= 1) u += __shfl_down_sync(0xffffffffu, u, o);
        if (lane == 0) g_bsums[blockIdx.x] = u;
    }
}

__global__ __launch_bounds__(1024) void k_scan3(int N, int nb) {
    __shared__ int sbs[MAX_SCAN_BLOCKS];
    __shared__ int ws[32];
    int t = threadIdx.x, lane = t & 31, wid = t >> 5;

    if (wid == 0) {
        int acc = 0;
#pragma unroll
        for (int c = 0; c < 4; c++) {
            int idx = c * 32 + lane;
            int v = (idx < nb) ? g_bsums[idx] : 0;
#pragma unroll
            for (int o = 1; o < 32; o <<= 1) {
                int u = __shfl_up_sync(0xffffffffu, v, o);
                if (lane >= o) v += u;
            }
            v += acc;
            sbs[idx] = v;
            acc = __shfl_sync(0xffffffffu, v, 31);
        }
    }

    int i = blockIdx.x * 1024 + t;
    int orig = (i < N) ? g_deg[i] : 0;
    int v = orig;
#pragma unroll
    for (int o = 1; o < 32; o <<= 1) {
        int u = __shfl_up_sync(0xffffffffu, v, o);
        if (lane >= o) v += u;
    }
    if (lane == 31) ws[wid] = v;
    __syncthreads();
    if (wid == 0) {
        int u = ws[lane];
#pragma unroll
        for (int o = 1; o < 32; o <<= 1) {
            int w2 = __shfl_up_sync(0xffffffffu, u, o);
            if (lane >= o) u += w2;
        }
        ws[lane] = u;
    }
    __syncthreads();
    int woff = (wid == 0) ? 0 : ws[wid - 1];
    int boff = (blockIdx.x == 0) ? 0 : sbs[blockIdx.x - 1];
    if (i < N) {
        int excl = boff + woff + v - orig;
        g_rowstart[i] = excl;
        g_cursor[i]   = excl;
    }
}

// ---------------- FUSED: scatter (CSR fill) + layer-1 GEMM ----------------
// Independent workloads with complementary bottlenecks (L2-atomic vs FMA/L1)
// run concurrently in one heterogeneous launch: blocks [0, gemmBlocks) do the
// gemm path, the rest do the scatter path.
__global__ __launch_bounds__(256) void k_scatter_gemm(
    const int* __restrict__ ei, int E,
    const float* __restrict__ x, const float* __restrict__ W1,
    const float* __restrict__ asw, const float* __restrict__ adw,
    int N, int gemmBlocks)
{
    int tid = threadIdx.x;
    if ((int)blockIdx.x < gemmBlocks) {
        // ---- gemm path (R6/R10 thread-per-node form) ----
        __shared__ float W1s[128 * 16];
        __shared__ float As[16], Ad[16];
        for (int i = tid; i < 128 * 16; i += 256) W1s[i] = W1[i];
        if (tid < 16) { As[tid] = asw[tid]; Ad[tid] = adw[tid]; }
        __syncthreads();

        int node = blockIdx.x * 256 + tid;
        if (node >= N) return;

        const float* xr = x + (size_t)node * 128;
        float acc[16];
#pragma unroll
        for (int j = 0; j < 16; j++) acc[j] = 0.f;

#pragma unroll
        for (int k4 = 0; k4 < 32; k4++) {
            float4 xv = ldg4(xr + k4 * 4);
            float xs[4] = {xv.x, xv.y, xv.z, xv.w};
#pragma unroll
            for (int i = 0; i < 4; i++) {
                const float* w = &W1s[(k4 * 4 + i) * 16];
                float xc = xs[i];
#pragma unroll
                for (int j = 0; j < 16; j++) acc[j] += xc * w[j];
            }
        }

        float asv[4], adv[4];
#pragma unroll
        for (int h = 0; h < 4; h++) {
            float4 hh = make_float4(acc[h*4+0], acc[h*4+1], acc[h*4+2], acc[h*4+3]);
            float4 av = make_float4(As[h*4+0], As[h*4+1], As[h*4+2], As[h*4+3]);
            float4 bv = make_float4(Ad[h*4+0], Ad[h*4+1], Ad[h*4+2], Ad[h*4+3]);
            asv[h] = dot4(hh, av);
            adv[h] = dot4(hh, bv);
        }

        __half2* h1p = g_h1h + (size_t)node * 8;
#pragma unroll
        for (int k = 0; k < 8; k++)
            h1p[k] = __floats2half2_rn(acc[2*k], acc[2*k+1]);
        *(float4*)(g_as1 + (size_t)node * 4) = make_float4(asv[0], asv[1], asv[2], asv[3]);
        *(float4*)(g_ad1 + (size_t)node * 4) = make_float4(adv[0], adv[1], adv[2], adv[3]);
    } else {
        // ---- scatter path ----
        int base = ((blockIdx.x - gemmBlocks) * 256 + tid) * 4;
#pragma unroll
        for (int k = 0; k < 4; k++) {
            int t = base + k;
            if (t < E) {
                int s = __ldg(&ei[t]);
                int d = __ldg(&ei[E + t]);
                int pos = atomicAdd(&g_cursor[d], 1);
                g_srcs[pos] = s;
            }
        }
    }
}

// ---------------- Layer 1 aggregation + FUSED layer-2 node stage (R8/R10 form) ----------------
__global__ __launch_bounds__(256) void k_agg1(
    const float* __restrict__ W2, const float* __restrict__ b1,
    const float* __restrict__ a2s, const float* __restrict__ a2d, int N)
{
    __shared__ float W2s[16 * 32];
    __shared__ float A2[32], B2[32], b1s[16];
    int tid = threadIdx.x;
    for (int i = tid; i < 512; i += 256) W2s[i] = W2[i];
    if (tid < 32) { A2[tid] = a2s[tid]; B2[tid] = a2d[tid]; }
    if (tid < 16) b1s[tid] = b1[tid];
    __syncthreads();

    int gid = blockIdx.x * 256 + tid;
    int d = gid >> 3;
    if (d >= N) return;
    int l = tid & 7;    // channel pair 0..7 (channels 2l, 2l+1)
    int h = l >> 1;     // head 0..3
    unsigned gmask = 0xffu << (tid & 24);

    float adh = g_ad1[d * 4 + h];
    float ash = g_as1[d * 4 + h];
    float2 hv0 = __half22float2(g_h1h[d * 8 + l]);
    float ee0 = expf(leakyf(ash + adh));   // self-loop
    float accx = ee0 * hv0.x, accy = ee0 * hv0.y;
    float den = ee0;

    int start = g_rowstart[d];
    int deg   = g_deg[d];
    int j = 0;
    for (; j + 4 <= deg; j += 4) {
        int s0 = __ldg(&g_srcs[start + j + 0]);
        int s1 = __ldg(&g_srcs[start + j + 1]);
        int s2 = __ldg(&g_srcs[start + j + 2]);
        int s3 = __ldg(&g_srcs[start + j + 3]);
        float a0 = __ldg(&g_as1[s0 * 4 + h]);
        float a1 = __ldg(&g_as1[s1 * 4 + h]);
        float a2 = __ldg(&g_as1[s2 * 4 + h]);
        float a3 = __ldg(&g_as1[s3 * 4 + h]);
        __half2 f0 = __ldg(&g_h1h[s0 * 8 + l]);
        __half2 f1 = __ldg(&g_h1h[s1 * 8 + l]);
        __half2 f2 = __ldg(&g_h1h[s2 * 8 + l]);
        __half2 f3 = __ldg(&g_h1h[s3 * 8 + l]);
        float e0 = expf(leakyf(a0 + adh));
        float e1 = expf(leakyf(a1 + adh));
        float e2 = expf(leakyf(a2 + adh));
        float e3 = expf(leakyf(a3 + adh));
        float2 g0 = __half22float2(f0), g1 = __half22float2(f1);
        float2 g2 = __half22float2(f2), g3 = __half22float2(f3);
        accx += e0 * g0.x + e1 * g1.x + e2 * g2.x + e3 * g3.x;
        accy += e0 * g0.y + e1 * g1.y + e2 * g2.y + e3 * g3.y;
        den  += (e0 + e1) + (e2 + e3);
    }
    for (; j < deg; j++) {
        int s = __ldg(&g_srcs[start + j]);
        float a = __ldg(&g_as1[s * 4 + h]);
        __half2 f = __ldg(&g_h1h[s * 8 + l]);
        float e = expf(leakyf(a + adh));
        float2 g = __half22float2(f);
        accx += e * g.x; accy += e * g.y; den += e;
    }

    // ---- fused layer-2 node stage ----
    float inv = 1.f / (den + 1e-16f);
    float h2a = mishf(accx * inv + b1s[2 * l]);
    float h2b = mishf(accy * inv + b1s[2 * l + 1]);

    float4 v = make_float4(0.f, 0.f, 0.f, 0.f);
#pragma unroll
    for (int k = 0; k < 16; k++) {
        float hk = (k & 1) ? __shfl_sync(gmask, h2b, k >> 1, 8)
                           : __shfl_sync(gmask, h2a, k >> 1, 8);
        fma4(v, hk, *(const float4*)&W2s[k * 32 + 4 * l]);
    }
    float as2 = dot4(v, *(const float4*)&A2[4 * l]);
    float ad2 = dot4(v, *(const float4*)&B2[4 * l]);
#pragma unroll
    for (int o = 4; o > 0; o >>= 1) {
        as2 += __shfl_xor_sync(gmask, as2, o, 8);
        ad2 += __shfl_xor_sync(gmask, ad2, o, 8);
    }

    __half2* vp = g_v2h + (size_t)d * 16 + 2 * l;
    vp[0] = __floats2half2_rn(v.x, v.y);
    vp[1] = __floats2half2_rn(v.z, v.w);
    if (l == 0) { g_as2[d] = as2; g_ad2[d] = ad2; }
}

// ---------------- Layer 2 aggregation, exp-deduplicated + FUSED mish epilogue ----------------
__global__ __launch_bounds__(256) void k_agg2(const float* __restrict__ b2, int N)
{
    int tid = threadIdx.x;
    int gid = blockIdx.x * 256 + tid;
    int d = gid >> 4;
    if (d >= N) return;
    int l = tid & 15;   // channel pair 0..15
    unsigned gmask = 0xffffu << (tid & 16);

    float ad  = g_ad2[d];
    float ee0 = expf(leakyf(g_as2[d] + ad));   // self-loop
    float2 vv0 = __half22float2(g_v2h[(size_t)d * 16 + l]);
    float accx = ee0 * vv0.x, accy = ee0 * vv0.y;
    float den = ee0;

    int start = g_rowstart[d];
    int deg   = g_deg[d];
    for (int j0 = 0; j0 < deg; j0 += 16) {
        int rem = deg - j0;
        int s_m = 0; float e_m = 0.f;
        if (l < rem) {
            s_m = __ldg(&g_srcs[start + j0 + l]);          // coalesced 16-wide
            e_m = expf(leakyf(__ldg(&g_as2[s_m]) + ad));   // ONE exp per edge
        }
        int kmax = min(rem, 16);
#pragma unroll 4
        for (int k = 0; k < kmax; k++) {
            int   s = __shfl_sync(gmask, s_m, k, 16);
            float e = __shfl_sync(gmask, e_m, k, 16);
            float2 g = __half22float2(__ldg(&g_v2h[(size_t)s * 16 + l]));
            accx += e * g.x; accy += e * g.y; den += e;
        }
    }

    float inv = 1.f / (den + 1e-16f);
    float oa = mishf(accx * inv + __ldg(&b2[2 * l]));
    float ob = mishf(accy * inv + __ldg(&b2[2 * l + 1]));
    g_out2h[(size_t)d * 16 + l] = __floats2half2_rn(oa, ob);
}

// ---------------- pool over half out2 ----------------
__global__ __launch_bounds__(256) void k_pool(
    const int* __restrict__ batch, int N, int chunk)
{
    __shared__ float ss[NG * 32];
    __shared__ int   sc[NG];
    int tid = threadIdx.x;
    for (int i = tid; i < NG * 32; i += 256) ss[i] = 0.f;
    if (tid < NG) sc[tid] = 0;
    __syncthreads();

    int start = blockIdx.x * chunk;
    int end   = min(N, start + chunk);
    int lane = tid & 31, w = tid >> 5;

    const __half* o2 = (const __half*)g_out2h;
    for (int node = start + w; node < end; node += 8) {
        int g = __ldg(&batch[node]);
        float val = __half2float(o2[(size_t)node * 32 + lane]);
        atomicAdd(&ss[g * 32 + lane], val);
        if (lane == 0) atomicAdd(&sc[g], 1);
    }
    __syncthreads();

    for (int i = tid; i < NG; i += 256)
        if (sc[i]) atomicAdd(&g_cnt[i], sc[i]);
    for (int i = tid; i < NG * 32; i += 256)
        if (sc[i >> 5]) atomicAdd(&g_sums[i], ss[i]);
}

__global__ void k_final(float* __restrict__ out)
{
    int t = blockIdx.x * blockDim.x + threadIdx.x;
    if (t < NG * 32)
        out[t] = g_sums[t] / fmaxf((float)g_cnt[t >> 5], 1.0f);
}

// ---------------- launch ----------------
extern "C" void kernel_launch(void* const* d_in, const int* in_sizes, int n_in,
                              void* d_out, int out_size)
{
    const float* x   = (const float*)d_in[0];
    const int*   ei  = (const int*)d_in[1];    // int32 [2,E]
    const int*   bat = (const int*)d_in[2];    // int32 [N]
    const float* W1  = (const float*)d_in[3];
    const float* b1  = (const float*)d_in[4];
    const float* a1s = (const float*)d_in[5];
    const float* a1d = (const float*)d_in[6];
    const float* W2  = (const float*)d_in[7];
    const float* b2  = (const float*)d_in[8];
    const float* a2s = (const float*)d_in[9];
    const float* a2d = (const float*)d_in[10];

    int N = in_sizes[0] / 128;
    int E = in_sizes[1] / 2;
    float* out = (float*)d_out;
    int nb = (N + 1023) / 1024;   // <=128

    k_zero<<<(N + 255) / 256, 256>>>(N);
    k_hist<<<(E + 1023) / 1024, 256>>>(ei, E);
    k_scan1<<<nb, 1024>>>(N);
    k_scan3<<<nb, 1024>>>(N, nb);

    // fused: CSR scatter + layer-1 GEMM run concurrently (independent work)
    int gemmBlocks = (N + 255) / 256;
    int scatBlocks = (E + 1023) / 1024;
    k_scatter_gemm<<<gemmBlocks + scatBlocks, 256>>>(ei, E, x, W1, a1s, a1d, N, gemmBlocks);

    // GAT layers (l2node fused into agg1; exp-dedup agg2 with fused mish)
    k_agg1<<<(N * 8 + 255) / 256, 256>>>(W2, b1, a2s, a2d, N);
    k_agg2<<<(N * 16 + 255) / 256, 256>>>(b2, N);

    int chunk = (N + 255) / 256;
    k_pool<<<256, 256>>>(bat, N, chunk);
    k_final<<<8, 256>>>(out);
}

// round 13
// speedup vs baseline: 1.0925x; 1.0086x over previous
#include <cuda_runtime.h>
#include <cuda_fp16.h>

#define NG   64
#define MAXN 100000
#define MAXE 3200000
#define MAX_SCAN_BLOCKS 128

// ---------------- scratch (device globals; no allocation allowed) ----------------
__device__ __align__(16) __half2 g_h1h[MAXN * 8];   // h1 as half2 (16 ch)
__device__ __align__(16) float2 g_efs1[MAXN * 4];   // (e^{as1}, e^{0.2 as1}) per head
__device__ __align__(16) float2 g_efd1[MAXN * 4];   // (e^{ad1}, e^{0.2 ad1}) per head
__device__ __align__(16) __half2 g_v2h[MAXN * 16];  // v2 as half2 (32 ch)
__device__ __align__(16) __half2 g_out2h[MAXN * 16];// out2 (post-mish) as half2
__device__ __align__(8) float2 g_efs2[MAXN];        // (e^{as2}, e^{0.2 as2})
__device__ __align__(8) float2 g_efd2[MAXN];        // (e^{ad2}, e^{0.2 ad2})
__device__ int   g_deg[MAXN];
__device__ int   g_rowstart[MAXN];
__device__ int   g_cursor[MAXN];
__device__ int   g_srcs[MAXE];
__device__ int   g_bsums[MAX_SCAN_BLOCKS];
__device__ __align__(16) float g_sums[NG * 32];
__device__ int   g_cnt[NG];

// ---------------- helpers ----------------
// mish(x) = x * tanh(softplus(x)) = x * (w^2-1)/(w^2+1), w = 1 + e^x  (exact identity)
__device__ __forceinline__ float mishq(float x) {
    float u  = __expf(x);
    float w  = 1.f + u;
    float w2 = w * w;
    float r  = x * __fdividef(w2 - 1.f, w2 + 1.f);
    return (x > 20.f) ? x : r;
}

__device__ __forceinline__ void fma4(float4& a, float s, float4 b) {
    a.x += s * b.x; a.y += s * b.y; a.z += s * b.z; a.w += s * b.w;
}
__device__ __forceinline__ float dot4(float4 a, float4 b) {
    return a.x * b.x + a.y * b.y + a.z * b.z + a.w * b.w;
}
__device__ __forceinline__ float4 ldg4(const float* p) {
    return __ldg((const float4*)p);
}

// ---------------- CSR build ----------------
__global__ void k_zero(int N) {
    int t = blockIdx.x * blockDim.x + threadIdx.x;
    if (t < N)       g_deg[t]  = 0;
    if (t < NG * 32) g_sums[t] = 0.f;
    if (t < NG)      g_cnt[t]  = 0;
}

__global__ __launch_bounds__(256) void k_hist(const int* __restrict__ ei, int E) {
    int base = (blockIdx.x * 256 + threadIdx.x) * 4;
#pragma unroll
    for (int k = 0; k < 4; k++) {
        int t = base + k;
        if (t < E) atomicAdd(&g_deg[__ldg(&ei[E + t])], 1);
    }
}

__global__ __launch_bounds__(1024) void k_scan1(int N) {
    __shared__ int ws[32];
    int t = threadIdx.x, lane = t & 31, wid = t >> 5;
    int i = blockIdx.x * 1024 + t;
    int v = (i < N) ? g_deg[i] : 0;
#pragma unroll
    for (int o = 16; o > 0; o >>= 1) v += __shfl_down_sync(0xffffffffu, v, o);
    if (lane == 0) ws[wid] = v;
    __syncthreads();
    if (wid == 0) {
        int u = ws[lane];
#pragma unroll
        for (int o = 16; o > 0; o >>= 1) u += __shfl_down_sync(0xffffffffu, u, o);
        if (lane == 0) g_bsums[blockIdx.x] = u;
    }
}

__global__ __launch_bounds__(1024) void k_scan3(int N, int nb) {
    __shared__ int sbs[MAX_SCAN_BLOCKS];
    __shared__ int ws[32];
    int t = threadIdx.x, lane = t & 31, wid = t >> 5;

    if (wid == 0) {
        int acc = 0;
#pragma unroll
        for (int c = 0; c < 4; c++) {
            int idx = c * 32 + lane;
            int v = (idx < nb) ? g_bsums[idx] : 0;
#pragma unroll
            for (int o = 1; o < 32; o <<= 1) {
                int u = __shfl_up_sync(0xffffffffu, v, o);
                if (lane >= o) v += u;
            }
            v += acc;
            sbs[idx] = v;
            acc = __shfl_sync(0xffffffffu, v, 31);
        }
    }

    int i = blockIdx.x * 1024 + t;
    int orig = (i < N) ? g_deg[i] : 0;
    int v = orig;
#pragma unroll
    for (int o = 1; o < 32; o <<= 1) {
        int u = __shfl_up_sync(0xffffffffu, v, o);
        if (lane >= o) v += u;
    }
    if (lane == 31) ws[wid] = v;
    __syncthreads();
    if (wid == 0) {
        int u = ws[lane];
#pragma unroll
        for (int o = 1; o < 32; o <<= 1) {
            int w2 = __shfl_up_sync(0xffffffffu, u, o);
            if (lane >= o) u += w2;
        }
        ws[lane] = u;
    }
    __syncthreads();
    int woff = (wid == 0) ? 0 : ws[wid - 1];
    int boff = (blockIdx.x == 0) ? 0 : sbs[blockIdx.x - 1];
    if (i < N) {
        int excl = boff + woff + v - orig;
        g_rowstart[i] = excl;
        g_cursor[i]   = excl;
    }
}

// ---------------- FUSED: scatter (CSR fill) + layer-1 GEMM ----------------
__global__ __launch_bounds__(256) void k_scatter_gemm(
    const int* __restrict__ ei, int E,
    const float* __restrict__ x, const float* __restrict__ W1,
    const float* __restrict__ asw, const float* __restrict__ adw,
    int N, int gemmBlocks)
{
    int tid = threadIdx.x;
    if ((int)blockIdx.x < gemmBlocks) {
        // ---- gemm path ----
        __shared__ float W1s[128 * 16];
        __shared__ float As[16], Ad[16];
        for (int i = tid; i < 128 * 16; i += 256) W1s[i] = W1[i];
        if (tid < 16) { As[tid] = asw[tid]; Ad[tid] = adw[tid]; }
        __syncthreads();

        int node = blockIdx.x * 256 + tid;
        if (node >= N) return;

        const float* xr = x + (size_t)node * 128;
        float acc[16];
#pragma unroll
        for (int j = 0; j < 16; j++) acc[j] = 0.f;

#pragma unroll
        for (int k4 = 0; k4 < 32; k4++) {
            float4 xv = ldg4(xr + k4 * 4);
            float xs[4] = {xv.x, xv.y, xv.z, xv.w};
#pragma unroll
            for (int i = 0; i < 4; i++) {
                const float* w = &W1s[(k4 * 4 + i) * 16];
                float xc = xs[i];
#pragma unroll
                for (int j = 0; j < 16; j++) acc[j] += xc * w[j];
            }
        }

        float es[4], fs[4], ed[4], fd[4];
#pragma unroll
        for (int h = 0; h < 4; h++) {
            float4 hh = make_float4(acc[h*4+0], acc[h*4+1], acc[h*4+2], acc[h*4+3]);
            float4 av = make_float4(As[h*4+0], As[h*4+1], As[h*4+2], As[h*4+3]);
            float4 bv = make_float4(Ad[h*4+0], Ad[h*4+1], Ad[h*4+2], Ad[h*4+3]);
            float asv = dot4(hh, av);
            float adv = dot4(hh, bv);
            es[h] = expf(asv); fs[h] = expf(0.2f * asv);
            ed[h] = expf(adv); fd[h] = expf(0.2f * adv);
        }

        __half2* h1p = g_h1h + (size_t)node * 8;
#pragma unroll
        for (int k = 0; k < 8; k++)
            h1p[k] = __floats2half2_rn(acc[2*k], acc[2*k+1]);
        float4* sp = (float4*)(g_efs1 + (size_t)node * 4);
        float4* dp = (float4*)(g_efd1 + (size_t)node * 4);
        sp[0] = make_float4(es[0], fs[0], es[1], fs[1]);
        sp[1] = make_float4(es[2], fs[2], es[3], fs[3]);
        dp[0] = make_float4(ed[0], fd[0], ed[1], fd[1]);
        dp[1] = make_float4(ed[2], fd[2], ed[3], fd[3]);
    } else {
        // ---- scatter path ----
        int base = ((blockIdx.x - gemmBlocks) * 256 + tid) * 4;
#pragma unroll
        for (int k = 0; k < 4; k++) {
            int t = base + k;
            if (t < E) {
                int s = __ldg(&ei[t]);
                int d = __ldg(&ei[E + t]);
                int pos = atomicAdd(&g_cursor[d], 1);
                g_srcs[pos] = s;
            }
        }
    }
}

// ---------------- Layer 1 aggregation + FUSED layer-2 node stage ----------------
// exp(leaky(as+ad)) = max(Es*Ed, Fs*Fd): zero per-edge transcendentals.
__global__ __launch_bounds__(256) void k_agg1(
    const float* __restrict__ W2, const float* __restrict__ b1,
    const float* __restrict__ a2s, const float* __restrict__ a2d, int N)
{
    __shared__ float W2s[16 * 32];
    __shared__ float A2[32], B2[32], b1s[16];
    int tid = threadIdx.x;
    for (int i = tid; i < 512; i += 256) W2s[i] = W2[i];
    if (tid < 32) { A2[tid] = a2s[tid]; B2[tid] = a2d[tid]; }
    if (tid < 16) b1s[tid] = b1[tid];
    __syncthreads();

    int gid = blockIdx.x * 256 + tid;
    int d = gid >> 3;
    if (d >= N) return;
    int l = tid & 7;    // channel pair 0..7 (channels 2l, 2l+1)
    int h = l >> 1;     // head 0..3
    unsigned gmask = 0xffu << (tid & 24);

    float2 D = __ldg(&g_efd1[d * 4 + h]);    // (Ed, Fd)
    float2 S0 = __ldg(&g_efs1[d * 4 + h]);
    float ee0 = fmaxf(S0.x * D.x, S0.y * D.y);   // self-loop
    float2 hv0 = __half22float2(g_h1h[d * 8 + l]);
    float accx = ee0 * hv0.x, accy = ee0 * hv0.y;
    float den = ee0;

    int start = g_rowstart[d];
    int deg   = g_deg[d];
    int j = 0;
    for (; j + 4 <= deg; j += 4) {
        int s0 = __ldg(&g_srcs[start + j + 0]);
        int s1 = __ldg(&g_srcs[start + j + 1]);
        int s2 = __ldg(&g_srcs[start + j + 2]);
        int s3 = __ldg(&g_srcs[start + j + 3]);
        float2 p0 = __ldg(&g_efs1[s0 * 4 + h]);
        float2 p1 = __ldg(&g_efs1[s1 * 4 + h]);
        float2 p2 = __ldg(&g_efs1[s2 * 4 + h]);
        float2 p3 = __ldg(&g_efs1[s3 * 4 + h]);
        __half2 f0 = __ldg(&g_h1h[s0 * 8 + l]);
        __half2 f1 = __ldg(&g_h1h[s1 * 8 + l]);
        __half2 f2 = __ldg(&g_h1h[s2 * 8 + l]);
        __half2 f3 = __ldg(&g_h1h[s3 * 8 + l]);
        float e0 = fmaxf(p0.x * D.x, p0.y * D.y);
        float e1 = fmaxf(p1.x * D.x, p1.y * D.y);
        float e2 = fmaxf(p2.x * D.x, p2.y * D.y);
        float e3 = fmaxf(p3.x * D.x, p3.y * D.y);
        float2 g0 = __half22float2(f0), g1 = __half22float2(f1);
        float2 g2 = __half22float2(f2), g3 = __half22float2(f3);
        accx += e0 * g0.x + e1 * g1.x + e2 * g2.x + e3 * g3.x;
        accy += e0 * g0.y + e1 * g1.y + e2 * g2.y + e3 * g3.y;
        den  += (e0 + e1) + (e2 + e3);
    }
    for (; j < deg; j++) {
        int s = __ldg(&g_srcs[start + j]);
        float2 p = __ldg(&g_efs1[s * 4 + h]);
        __half2 f = __ldg(&g_h1h[s * 8 + l]);
        float e = fmaxf(p.x * D.x, p.y * D.y);
        float2 g = __half22float2(f);
        accx += e * g.x; accy += e * g.y; den += e;
    }

    // ---- fused layer-2 node stage ----
    float inv = 1.f / (den + 1e-16f);
    float h2a = mishq(accx * inv + b1s[2 * l]);
    float h2b = mishq(accy * inv + b1s[2 * l + 1]);

    float4 v = make_float4(0.f, 0.f, 0.f, 0.f);
#pragma unroll
    for (int k = 0; k < 16; k++) {
        float hk = (k & 1) ? __shfl_sync(gmask, h2b, k >> 1, 8)
                           : __shfl_sync(gmask, h2a, k >> 1, 8);
        fma4(v, hk, *(const float4*)&W2s[k * 32 + 4 * l]);
    }
    float as2 = dot4(v, *(const float4*)&A2[4 * l]);
    float ad2 = dot4(v, *(const float4*)&B2[4 * l]);
#pragma unroll
    for (int o = 4; o > 0; o >>= 1) {
        as2 += __shfl_xor_sync(gmask, as2, o, 8);
        ad2 += __shfl_xor_sync(gmask, ad2, o, 8);
    }

    __half2* vp = g_v2h + (size_t)d * 16 + 2 * l;
    vp[0] = __floats2half2_rn(v.x, v.y);
    vp[1] = __floats2half2_rn(v.z, v.w);
    if (l == 0) g_efs2[d] = make_float2(expf(as2), expf(0.2f * as2));
    if (l == 1) g_efd2[d] = make_float2(expf(ad2), expf(0.2f * ad2));
}

// ---------------- Layer 2 aggregation (mul-trick) + FUSED mish epilogue ----------------
__global__ __launch_bounds__(256) void k_agg2(const float* __restrict__ b2, int N)
{
    int tid = threadIdx.x;
    int gid = blockIdx.x * 256 + tid;
    int d = gid >> 4;
    if (d >= N) return;
    int l = tid & 15;   // channel pair 0..15

    float2 D = __ldg(&g_efd2[d]);            // (Ed, Fd)
    float2 S0 = __ldg(&g_efs2[d]);
    float ee0 = fmaxf(S0.x * D.x, S0.y * D.y);   // self-loop
    float2 vv0 = __half22float2(g_v2h[(size_t)d * 16 + l]);
    float accx = ee0 * vv0.x, accy = ee0 * vv0.y;
    float den = ee0;

    int start = g_rowstart[d];
    int deg   = g_deg[d];
    int j = 0;
    for (; j + 4 <= deg; j += 4) {
        int s0 = __ldg(&g_srcs[start + j + 0]);
        int s1 = __ldg(&g_srcs[start + j + 1]);
        int s2 = __ldg(&g_srcs[start + j + 2]);
        int s3 = __ldg(&g_srcs[start + j + 3]);
        float2 p0 = __ldg(&g_efs2[s0]);
        float2 p1 = __ldg(&g_efs2[s1]);
        float2 p2 = __ldg(&g_efs2[s2]);
        float2 p3 = __ldg(&g_efs2[s3]);
        __half2 f0 = __ldg(&g_v2h[(size_t)s0 * 16 + l]);
        __half2 f1 = __ldg(&g_v2h[(size_t)s1 * 16 + l]);
        __half2 f2 = __ldg(&g_v2h[(size_t)s2 * 16 + l]);
        __half2 f3 = __ldg(&g_v2h[(size_t)s3 * 16 + l]);
        float e0 = fmaxf(p0.x * D.x, p0.y * D.y);
        float e1 = fmaxf(p1.x * D.x, p1.y * D.y);
        float e2 = fmaxf(p2.x * D.x, p2.y * D.y);
        float e3 = fmaxf(p3.x * D.x, p3.y * D.y);
        float2 g0 = __half22float2(f0), g1 = __half22float2(f1);
        float2 g2 = __half22float2(f2), g3 = __half22float2(f3);
        accx += e0 * g0.x + e1 * g1.x + e2 * g2.x + e3 * g3.x;
        accy += e0 * g0.y + e1 * g1.y + e2 * g2.y + e3 * g3.y;
        den  += (e0 + e1) + (e2 + e3);
    }
    for (; j < deg; j++) {
        int s = __ldg(&g_srcs[start + j]);
        float2 p = __ldg(&g_efs2[s]);
        __half2 f = __ldg(&g_v2h[(size_t)s * 16 + l]);
        float e = fmaxf(p.x * D.x, p.y * D.y);
        float2 g = __half22float2(f);
        accx += e * g.x; accy += e * g.y; den += e;
    }

    float inv = 1.f / (den + 1e-16f);
    float oa = mishq(accx * inv + __ldg(&b2[2 * l]));
    float ob = mishq(accy * inv + __ldg(&b2[2 * l + 1]));
    g_out2h[(size_t)d * 16 + l] = __floats2half2_rn(oa, ob);
}

// ---------------- pool over half out2 ----------------
__global__ __launch_bounds__(256) void k_pool(
    const int* __restrict__ batch, int N, int chunk)
{
    __shared__ float ss[NG * 32];
    __shared__ int   sc[NG];
    int tid = threadIdx.x;
    for (int i = tid; i < NG * 32; i += 256) ss[i] = 0.f;
    if (tid < NG) sc[tid] = 0;
    __syncthreads();

    int start = blockIdx.x * chunk;
    int end   = min(N, start + chunk);
    int lane = tid & 31, w = tid >> 5;

    const __half* o2 = (const __half*)g_out2h;
    for (int node = start + w; node < end; node += 8) {
        int g = __ldg(&batch[node]);
        float val = __half2float(o2[(size_t)node * 32 + lane]);
        atomicAdd(&ss[g * 32 + lane], val);
        if (lane == 0) atomicAdd(&sc[g], 1);
    }
    __syncthreads();

    for (int i = tid; i < NG; i += 256)
        if (sc[i]) atomicAdd(&g_cnt[i], sc[i]);
    for (int i = tid; i < NG * 32; i += 256)
        if (sc[i >> 5]) atomicAdd(&g_sums[i], ss[i]);
}

__global__ void k_final(float* __restrict__ out)
{
    int t = blockIdx.x * blockDim.x + threadIdx.x;
    if (t < NG * 32)
        out[t] = g_sums[t] / fmaxf((float)g_cnt[t >> 5], 1.0f);
}

// ---------------- launch ----------------
extern "C" void kernel_launch(void* const* d_in, const int* in_sizes, int n_in,
                              void* d_out, int out_size)
{
    const float* x   = (const float*)d_in[0];
    const int*   ei  = (const int*)d_in[1];    // int32 [2,E]
    const int*   bat = (const int*)d_in[2];    // int32 [N]
    const float* W1  = (const float*)d_in[3];
    const float* b1  = (const float*)d_in[4];
    const float* a1s = (const float*)d_in[5];
    const float* a1d = (const float*)d_in[6];
    const float* W2  = (const float*)d_in[7];
    const float* b2  = (const float*)d_in[8];
    const float* a2s = (const float*)d_in[9];
    const float* a2d = (const float*)d_in[10];

    int N = in_sizes[0] / 128;
    int E = in_sizes[1] / 2;
    float* out = (float*)d_out;
    int nb = (N + 1023) / 1024;   // <=128

    k_zero<<<(N + 255) / 256, 256>>>(N);
    k_hist<<<(E + 1023) / 1024, 256>>>(ei, E);
    k_scan1<<<nb, 1024>>>(N);
    k_scan3<<<nb, 1024>>>(N, nb);

    // fused: CSR scatter + layer-1 GEMM run concurrently (independent work)
    int gemmBlocks = (N + 255) / 256;
    int scatBlocks = (E + 1023) / 1024;
    k_scatter_gemm<<<gemmBlocks + scatBlocks, 256>>>(ei, E, x, W1, a1s, a1d, N, gemmBlocks);

    // GAT layers (mul-trick: zero per-edge transcendentals)
    k_agg1<<<(N * 8 + 255) / 256, 256>>>(W2, b1, a2s, a2d, N);
    k_agg2<<<(N * 16 + 255) / 256, 256>>>(b2, N);

    int chunk = (N + 255) / 256;
    k_pool<<<256, 256>>>(bat, N, chunk);
    k_final<<<8, 256>>>(out);
}

// round 14
// speedup vs baseline: 1.2710x; 1.1635x over previous
#include <cuda_runtime.h>
#include <cuda_fp16.h>

#define NG   64
#define MAXN 100000
#define MAXE 3200000
#define MAX_SCAN_BLOCKS 128

// ---------------- scratch (device globals; no allocation allowed) ----------------
__device__ __align__(16) __half2 g_h1h[MAXN * 8];   // h1 as half2 (16 ch)
__device__ __align__(16) float2 g_efs1[MAXN * 4];   // (e^{as1}, e^{0.2 as1}) per head
__device__ __align__(16) float2 g_efd1[MAXN * 4];   // (e^{ad1}, e^{0.2 ad1}) per head
__device__ __align__(16) __half2 g_v2h[MAXN * 16];  // v2 as half2 (32 ch)
__device__ __align__(16) __half2 g_out2h[MAXN * 16];// out2 (post-mish) as half2
__device__ __align__(8) float2 g_efs2[MAXN];        // (e^{as2}, e^{0.2 as2})
__device__ __align__(8) float2 g_efd2[MAXN];        // (e^{ad2}, e^{0.2 ad2})
__device__ int   g_deg[MAXN];
__device__ int   g_rowstart[MAXN];
__device__ int   g_cursor[MAXN];
__device__ int   g_srcs[MAXE];
__device__ int   g_bsums[MAX_SCAN_BLOCKS];
__device__ __align__(16) float g_sums[NG * 32];
__device__ int   g_cnt[NG];

// ---------------- helpers ----------------
// mish(x) = x * (w^2-1)/(w^2+1), w = 1 + e^x  (exact identity)
__device__ __forceinline__ float mishq(float x) {
    float u  = __expf(x);
    float w  = 1.f + u;
    float w2 = w * w;
    float r  = x * __fdividef(w2 - 1.f, w2 + 1.f);
    return (x > 20.f) ? x : r;
}

__device__ __forceinline__ void fma4(float4& a, float s, float4 b) {
    a.x += s * b.x; a.y += s * b.y; a.z += s * b.z; a.w += s * b.w;
}
__device__ __forceinline__ float dot4(float4 a, float4 b) {
    return a.x * b.x + a.y * b.y + a.z * b.z + a.w * b.w;
}
__device__ __forceinline__ float4 ldg4(const float* p) {
    return __ldg((const float4*)p);
}
// load 2 half2 (8B) and convert to 4 floats
__device__ __forceinline__ void ldcvt4(const __half2* p, float2& a, float2& b) {
    uint2 r = __ldg((const uint2*)p);
    __half2 h0 = *(__half2*)&r.x;
    __half2 h1 = *(__half2*)&r.y;
    a = __half22float2(h0);
    b = __half22float2(h1);
}

// ---------------- CSR build ----------------
__global__ void k_zero(int N) {
    int t = blockIdx.x * blockDim.x + threadIdx.x;
    if (t < N)       g_deg[t]  = 0;
    if (t < NG * 32) g_sums[t] = 0.f;
    if (t < NG)      g_cnt[t]  = 0;
}

__global__ __launch_bounds__(256) void k_hist(const int* __restrict__ ei, int E) {
    int base = (blockIdx.x * 256 + threadIdx.x) * 4;
#pragma unroll
    for (int k = 0; k < 4; k++) {
        int t = base + k;
        if (t < E) atomicAdd(&g_deg[__ldg(&ei[E + t])], 1);
    }
}

__global__ __launch_bounds__(1024) void k_scan1(int N) {
    __shared__ int ws[32];
    int t = threadIdx.x, lane = t & 31, wid = t >> 5;
    int i = blockIdx.x * 1024 + t;
    int v = (i < N) ? g_deg[i] : 0;
#pragma unroll
    for (int o = 16; o > 0; o >>= 1) v += __shfl_down_sync(0xffffffffu, v, o);
    if (lane == 0) ws[wid] = v;
    __syncthreads();
    if (wid == 0) {
        int u = ws[lane];
#pragma unroll
        for (int o = 16; o > 0; o >>= 1) u += __shfl_down_sync(0xffffffffu, u, o);
        if (lane == 0) g_bsums[blockIdx.x] = u;
    }
}

__global__ __launch_bounds__(1024) void k_scan3(int N, int nb) {
    __shared__ int sbs[MAX_SCAN_BLOCKS];
    __shared__ int ws[32];
    int t = threadIdx.x, lane = t & 31, wid = t >> 5;

    if (wid == 0) {
        int acc = 0;
#pragma unroll
        for (int c = 0; c < 4; c++) {
            int idx = c * 32 + lane;
            int v = (idx < nb) ? g_bsums[idx] : 0;
#pragma unroll
            for (int o = 1; o < 32; o <<= 1) {
                int u = __shfl_up_sync(0xffffffffu, v, o);
                if (lane >= o) v += u;
            }
            v += acc;
            sbs[idx] = v;
            acc = __shfl_sync(0xffffffffu, v, 31);
        }
    }

    int i = blockIdx.x * 1024 + t;
    int orig = (i < N) ? g_deg[i] : 0;
    int v = orig;
#pragma unroll
    for (int o = 1; o < 32; o <<= 1) {
        int u = __shfl_up_sync(0xffffffffu, v, o);
        if (lane >= o) v += u;
    }
    if (lane == 31) ws[wid] = v;
    __syncthreads();
    if (wid == 0) {
        int u = ws[lane];
#pragma unroll
        for (int o = 1; o < 32; o <<= 1) {
            int w2 = __shfl_up_sync(0xffffffffu, u, o);
            if (lane >= o) u += w2;
        }
        ws[lane] = u;
    }
    __syncthreads();
    int woff = (wid == 0) ? 0 : ws[wid - 1];
    int boff = (blockIdx.x == 0) ? 0 : sbs[blockIdx.x - 1];
    if (i < N) {
        int excl = boff + woff + v - orig;
        g_rowstart[i] = excl;
        g_cursor[i]   = excl;
    }
}

// ---------------- FUSED: scatter (CSR fill) + layer-1 GEMM ----------------
__global__ __launch_bounds__(256) void k_scatter_gemm(
    const int* __restrict__ ei, int E,
    const float* __restrict__ x, const float* __restrict__ W1,
    const float* __restrict__ asw, const float* __restrict__ adw,
    int N, int gemmBlocks)
{
    int tid = threadIdx.x;
    if ((int)blockIdx.x < gemmBlocks) {
        __shared__ float W1s[128 * 16];
        __shared__ float As[16], Ad[16];
        for (int i = tid; i < 128 * 16; i += 256) W1s[i] = W1[i];
        if (tid < 16) { As[tid] = asw[tid]; Ad[tid] = adw[tid]; }
        __syncthreads();

        int node = blockIdx.x * 256 + tid;
        if (node >= N) return;

        const float* xr = x + (size_t)node * 128;
        float acc[16];
#pragma unroll
        for (int j = 0; j < 16; j++) acc[j] = 0.f;

#pragma unroll
        for (int k4 = 0; k4 < 32; k4++) {
            float4 xv = ldg4(xr + k4 * 4);
            float xs[4] = {xv.x, xv.y, xv.z, xv.w};
#pragma unroll
            for (int i = 0; i < 4; i++) {
                const float* w = &W1s[(k4 * 4 + i) * 16];
                float xc = xs[i];
#pragma unroll
                for (int j = 0; j < 16; j++) acc[j] += xc * w[j];
            }
        }

        float es[4], fs[4], ed[4], fd[4];
#pragma unroll
        for (int h = 0; h < 4; h++) {
            float4 hh = make_float4(acc[h*4+0], acc[h*4+1], acc[h*4+2], acc[h*4+3]);
            float4 av = make_float4(As[h*4+0], As[h*4+1], As[h*4+2], As[h*4+3]);
            float4 bv = make_float4(Ad[h*4+0], Ad[h*4+1], Ad[h*4+2], Ad[h*4+3]);
            float asv = dot4(hh, av);
            float adv = dot4(hh, bv);
            es[h] = expf(asv); fs[h] = expf(0.2f * asv);
            ed[h] = expf(adv); fd[h] = expf(0.2f * adv);
        }

        __half2* h1p = g_h1h + (size_t)node * 8;
#pragma unroll
        for (int k = 0; k < 8; k++)
            h1p[k] = __floats2half2_rn(acc[2*k], acc[2*k+1]);
        float4* sp = (float4*)(g_efs1 + (size_t)node * 4);
        float4* dp = (float4*)(g_efd1 + (size_t)node * 4);
        sp[0] = make_float4(es[0], fs[0], es[1], fs[1]);
        sp[1] = make_float4(es[2], fs[2], es[3], fs[3]);
        dp[0] = make_float4(ed[0], fd[0], ed[1], fd[1]);
        dp[1] = make_float4(ed[2], fd[2], ed[3], fd[3]);
    } else {
        int base = ((blockIdx.x - gemmBlocks) * 256 + tid) * 4;
#pragma unroll
        for (int k = 0; k < 4; k++) {
            int t = base + k;
            if (t < E) {
                int s = __ldg(&ei[t]);
                int d = __ldg(&ei[E + t]);
                int pos = atomicAdd(&g_cursor[d], 1);
                g_srcs[pos] = s;
            }
        }
    }
}

// ---------------- Layer 1 agg: 4 lanes/dst (lane = head), LDG.64 features ----------------
__global__ __launch_bounds__(256) void k_agg1(
    const float* __restrict__ W2, const float* __restrict__ b1,
    const float* __restrict__ a2s, const float* __restrict__ a2d, int N)
{
    __shared__ float W2s[16 * 32];
    __shared__ float A2[32], B2[32], b1s[16];
    int tid = threadIdx.x;
    for (int i = tid; i < 512; i += 256) W2s[i] = W2[i];
    if (tid < 32) { A2[tid] = a2s[tid]; B2[tid] = a2d[tid]; }
    if (tid < 16) b1s[tid] = b1[tid];
    __syncthreads();

    int gid = blockIdx.x * 256 + tid;
    int d = gid >> 2;
    if (d >= N) return;
    int q = tid & 3;    // head; channels 4q..4q+3
    unsigned gmask = 0xfu << (tid & 28);

    float2 D  = __ldg(&g_efd1[d * 4 + q]);   // (Ed, Fd) for this head
    float2 S0 = __ldg(&g_efs1[d * 4 + q]);
    float ee0 = fmaxf(S0.x * D.x, S0.y * D.y);   // self-loop
    float2 c0, c1;
    ldcvt4(&g_h1h[(size_t)d * 8 + 2 * q], c0, c1);
    float a0 = ee0 * c0.x, a1 = ee0 * c0.y, a2v = ee0 * c1.x, a3 = ee0 * c1.y;
    float den = ee0;

    int start = g_rowstart[d];
    int deg   = g_deg[d];
    int j = 0;
    for (; j + 4 <= deg; j += 4) {
        int s0 = __ldg(&g_srcs[start + j + 0]);
        int s1 = __ldg(&g_srcs[start + j + 1]);
        int s2 = __ldg(&g_srcs[start + j + 2]);
        int s3 = __ldg(&g_srcs[start + j + 3]);
        float2 p0 = __ldg(&g_efs1[s0 * 4 + q]);
        float2 p1 = __ldg(&g_efs1[s1 * 4 + q]);
        float2 p2 = __ldg(&g_efs1[s2 * 4 + q]);
        float2 p3 = __ldg(&g_efs1[s3 * 4 + q]);
        float2 x0, y0, x1, y1, x2, y2, x3, y3;
        ldcvt4(&g_h1h[(size_t)s0 * 8 + 2 * q], x0, y0);
        ldcvt4(&g_h1h[(size_t)s1 * 8 + 2 * q], x1, y1);
        ldcvt4(&g_h1h[(size_t)s2 * 8 + 2 * q], x2, y2);
        ldcvt4(&g_h1h[(size_t)s3 * 8 + 2 * q], x3, y3);
        float e0 = fmaxf(p0.x * D.x, p0.y * D.y);
        float e1 = fmaxf(p1.x * D.x, p1.y * D.y);
        float e2 = fmaxf(p2.x * D.x, p2.y * D.y);
        float e3 = fmaxf(p3.x * D.x, p3.y * D.y);
        a0  += e0 * x0.x + e1 * x1.x + e2 * x2.x + e3 * x3.x;
        a1  += e0 * x0.y + e1 * x1.y + e2 * x2.y + e3 * x3.y;
        a2v += e0 * y0.x + e1 * y1.x + e2 * y2.x + e3 * y3.x;
        a3  += e0 * y0.y + e1 * y1.y + e2 * y2.y + e3 * y3.y;
        den += (e0 + e1) + (e2 + e3);
    }
    for (; j < deg; j++) {
        int s = __ldg(&g_srcs[start + j]);
        float2 p = __ldg(&g_efs1[s * 4 + q]);
        float2 xx, yy;
        ldcvt4(&g_h1h[(size_t)s * 8 + 2 * q], xx, yy);
        float e = fmaxf(p.x * D.x, p.y * D.y);
        a0 += e * xx.x; a1 += e * xx.y; a2v += e * yy.x; a3 += e * yy.y;
        den += e;
    }

    // ---- fused layer-2 node stage (4-lane group) ----
    float inv = 1.f / (den + 1e-16f);
    float h2r[4];
    h2r[0] = mishq(a0  * inv + b1s[4 * q + 0]);
    h2r[1] = mishq(a1  * inv + b1s[4 * q + 1]);
    h2r[2] = mishq(a2v * inv + b1s[4 * q + 2]);
    h2r[3] = mishq(a3  * inv + b1s[4 * q + 3]);

    float4 vlo = make_float4(0.f, 0.f, 0.f, 0.f);
    float4 vhi = make_float4(0.f, 0.f, 0.f, 0.f);
#pragma unroll
    for (int k = 0; k < 16; k++) {
        float hk = __shfl_sync(gmask, h2r[k & 3], k >> 2, 4);
        const float4* w = (const float4*)&W2s[k * 32 + 8 * q];
        fma4(vlo, hk, w[0]);
        fma4(vhi, hk, w[1]);
    }
    float as2 = dot4(vlo, *(const float4*)&A2[8 * q]) + dot4(vhi, *(const float4*)&A2[8 * q + 4]);
    float ad2 = dot4(vlo, *(const float4*)&B2[8 * q]) + dot4(vhi, *(const float4*)&B2[8 * q + 4]);
#pragma unroll
    for (int o = 2; o > 0; o >>= 1) {
        as2 += __shfl_xor_sync(gmask, as2, o, 4);
        ad2 += __shfl_xor_sync(gmask, ad2, o, 4);
    }

    union { uint4 u; __half2 h[4]; } P;
    P.h[0] = __floats2half2_rn(vlo.x, vlo.y);
    P.h[1] = __floats2half2_rn(vlo.z, vlo.w);
    P.h[2] = __floats2half2_rn(vhi.x, vhi.y);
    P.h[3] = __floats2half2_rn(vhi.z, vhi.w);
    *(uint4*)(g_v2h + (size_t)d * 16 + 4 * q) = P.u;
    if (q == 0) g_efs2[d] = make_float2(expf(as2), expf(0.2f * as2));
    if (q == 1) g_efd2[d] = make_float2(expf(ad2), expf(0.2f * ad2));
}

// ---------------- Layer 2 agg: 8 lanes/dst, LDG.64 features + fused mish ----------------
__global__ __launch_bounds__(256) void k_agg2(const float* __restrict__ b2, int N)
{
    int tid = threadIdx.x;
    int gid = blockIdx.x * 256 + tid;
    int d = gid >> 3;
    if (d >= N) return;
    int l = tid & 7;    // channels 4l..4l+3

    float2 D  = __ldg(&g_efd2[d]);
    float2 S0 = __ldg(&g_efs2[d]);
    float ee0 = fmaxf(S0.x * D.x, S0.y * D.y);   // self-loop
    float2 c0, c1;
    ldcvt4(&g_v2h[(size_t)d * 16 + 2 * l], c0, c1);
    float a0 = ee0 * c0.x, a1 = ee0 * c0.y, a2v = ee0 * c1.x, a3 = ee0 * c1.y;
    float den = ee0;

    int start = g_rowstart[d];
    int deg   = g_deg[d];
    int j = 0;
    for (; j + 4 <= deg; j += 4) {
        int s0 = __ldg(&g_srcs[start + j + 0]);
        int s1 = __ldg(&g_srcs[start + j + 1]);
        int s2 = __ldg(&g_srcs[start + j + 2]);
        int s3 = __ldg(&g_srcs[start + j + 3]);
        float2 p0 = __ldg(&g_efs2[s0]);
        float2 p1 = __ldg(&g_efs2[s1]);
        float2 p2 = __ldg(&g_efs2[s2]);
        float2 p3 = __ldg(&g_efs2[s3]);
        float2 x0, y0, x1, y1, x2, y2, x3, y3;
        ldcvt4(&g_v2h[(size_t)s0 * 16 + 2 * l], x0, y0);
        ldcvt4(&g_v2h[(size_t)s1 * 16 + 2 * l], x1, y1);
        ldcvt4(&g_v2h[(size_t)s2 * 16 + 2 * l], x2, y2);
        ldcvt4(&g_v2h[(size_t)s3 * 16 + 2 * l], x3, y3);
        float e0 = fmaxf(p0.x * D.x, p0.y * D.y);
        float e1 = fmaxf(p1.x * D.x, p1.y * D.y);
        float e2 = fmaxf(p2.x * D.x, p2.y * D.y);
        float e3 = fmaxf(p3.x * D.x, p3.y * D.y);
        a0  += e0 * x0.x + e1 * x1.x + e2 * x2.x + e3 * x3.x;
        a1  += e0 * x0.y + e1 * x1.y + e2 * x2.y + e3 * x3.y;
        a2v += e0 * y0.x + e1 * y1.x + e2 * y2.x + e3 * y3.x;
        a3  += e0 * y0.y + e1 * y1.y + e2 * y2.y + e3 * y3.y;
        den += (e0 + e1) + (e2 + e3);
    }
    for (; j < deg; j++) {
        int s = __ldg(&g_srcs[start + j]);
        float2 p = __ldg(&g_efs2[s]);
        float2 xx, yy;
        ldcvt4(&g_v2h[(size_t)s * 16 + 2 * l], xx, yy);
        float e = fmaxf(p.x * D.x, p.y * D.y);
        a0 += e * xx.x; a1 += e * xx.y; a2v += e * yy.x; a3 += e * yy.y;
        den += e;
    }

    float inv = 1.f / (den + 1e-16f);
    float o0 = mishq(a0  * inv + __ldg(&b2[4 * l + 0]));
    float o1 = mishq(a1  * inv + __ldg(&b2[4 * l + 1]));
    float o2 = mishq(a2v * inv + __ldg(&b2[4 * l + 2]));
    float o3 = mishq(a3  * inv + __ldg(&b2[4 * l + 3]));
    union { uint2 u; __half2 h[2]; } P;
    P.h[0] = __floats2half2_rn(o0, o1);
    P.h[1] = __floats2half2_rn(o2, o3);
    *(uint2*)(g_out2h + (size_t)d * 16 + 2 * l) = P.u;
}

// ---------------- pool over half out2 ----------------
__global__ __launch_bounds__(256) void k_pool(
    const int* __restrict__ batch, int N, int chunk)
{
    __shared__ float ss[NG * 32];
    __shared__ int   sc[NG];
    int tid = threadIdx.x;
    for (int i = tid; i < NG * 32; i += 256) ss[i] = 0.f;
    if (tid < NG) sc[tid] = 0;
    __syncthreads();

    int start = blockIdx.x * chunk;
    int end   = min(N, start + chunk);
    int lane = tid & 31, w = tid >> 5;

    const __half* o2 = (const __half*)g_out2h;
    for (int node = start + w; node < end; node += 8) {
        int g = __ldg(&batch[node]);
        float val = __half2float(o2[(size_t)node * 32 + lane]);
        atomicAdd(&ss[g * 32 + lane], val);
        if (lane == 0) atomicAdd(&sc[g], 1);
    }
    __syncthreads();

    for (int i = tid; i < NG; i += 256)
        if (sc[i]) atomicAdd(&g_cnt[i], sc[i]);
    for (int i = tid; i < NG * 32; i += 256)
        if (sc[i >> 5]) atomicAdd(&g_sums[i], ss[i]);
}

__global__ void k_final(float* __restrict__ out)
{
    int t = blockIdx.x * blockDim.x + threadIdx.x;
    if (t < NG * 32)
        out[t] = g_sums[t] / fmaxf((float)g_cnt[t >> 5], 1.0f);
}

// ---------------- launch ----------------
extern "C" void kernel_launch(void* const* d_in, const int* in_sizes, int n_in,
                              void* d_out, int out_size)
{
    const float* x   = (const float*)d_in[0];
    const int*   ei  = (const int*)d_in[1];    // int32 [2,E]
    const int*   bat = (const int*)d_in[2];    // int32 [N]
    const float* W1  = (const float*)d_in[3];
    const float* b1  = (const float*)d_in[4];
    const float* a1s = (const float*)d_in[5];
    const float* a1d = (const float*)d_in[6];
    const float* W2  = (const float*)d_in[7];
    const float* b2  = (const float*)d_in[8];
    const float* a2s = (const float*)d_in[9];
    const float* a2d = (const float*)d_in[10];

    int N = in_sizes[0] / 128;
    int E = in_sizes[1] / 2;
    float* out = (float*)d_out;
    int nb = (N + 1023) / 1024;   // <=128

    k_zero<<<(N + 255) / 256, 256>>>(N);
    k_hist<<<(E + 1023) / 1024, 256>>>(ei, E);
    k_scan1<<<nb, 1024>>>(N);
    k_scan3<<<nb, 1024>>>(N, nb);

    // fused: CSR scatter + layer-1 GEMM run concurrently (independent work)
    int gemmBlocks = (N + 255) / 256;
    int scatBlocks = (E + 1023) / 1024;
    k_scatter_gemm<<<gemmBlocks + scatBlocks, 256>>>(ei, E, x, W1, a1s, a1d, N, gemmBlocks);

    // GAT layers (narrow groups + wide loads: fewer LDG issues per edge)
    k_agg1<<<(N * 4 + 255) / 256, 256>>>(W2, b1, a2s, a2d, N);
    k_agg2<<<(N * 8 + 255) / 256, 256>>>(b2, N);

    int chunk = (N + 255) / 256;
    k_pool<<<256, 256>>>(bat, N, chunk);
    k_final<<<8, 256>>>(out);
}